// round 1
// baseline (speedup 1.0000x reference)
#include <cuda_runtime.h>

// Fixed problem shape (from reference): N = 100,000 nodes.
#define MAX_NODES 100000

// Scratch: degree accumulators, later overwritten in-place with rsqrt(deg).
__device__ float g_outdeg[MAX_NODES];
__device__ float g_indeg[MAX_NODES];

// ---------------------------------------------------------------------------
// Kernel 1: zero the accumulators (d_out is poisoned; these are device globals
// that persist across graph replays, so they MUST be re-zeroed every launch).
// ---------------------------------------------------------------------------
__global__ void zero_deg_kernel() {
    int i = blockIdx.x * blockDim.x + threadIdx.x;
    if (i < MAX_NODES) {
        g_outdeg[i] = 0.0f;
        g_indeg[i]  = 0.0f;
    }
}

// ---------------------------------------------------------------------------
// Kernel 2: scatter edge weights into out-degree (by src) and in-degree (by
// dst). Vectorized: each thread < n4 handles 4 edges via float4/int4 loads;
// tail threads handle the scalar remainder.
// atomicAdd with unused return -> REDG (no round trip).
// ---------------------------------------------------------------------------
__global__ void scatter_deg_kernel(const float4* __restrict__ w4,
                                   const int4*   __restrict__ s4,
                                   const int4*   __restrict__ d4,
                                   const float*  __restrict__ w,
                                   const int*    __restrict__ s,
                                   const int*    __restrict__ d,
                                   int n4, int E) {
    int tid = blockIdx.x * blockDim.x + threadIdx.x;
    if (tid < n4) {
        float4 wv = w4[tid];
        int4   sv = s4[tid];
        int4   dv = d4[tid];
        atomicAdd(&g_outdeg[sv.x], wv.x);
        atomicAdd(&g_outdeg[sv.y], wv.y);
        atomicAdd(&g_outdeg[sv.z], wv.z);
        atomicAdd(&g_outdeg[sv.w], wv.w);
        atomicAdd(&g_indeg[dv.x], wv.x);
        atomicAdd(&g_indeg[dv.y], wv.y);
        atomicAdd(&g_indeg[dv.z], wv.z);
        atomicAdd(&g_indeg[dv.w], wv.w);
    } else {
        int i = 4 * n4 + (tid - n4);
        if (i < E) {
            float wv = w[i];
            atomicAdd(&g_outdeg[s[i]], wv);
            atomicAdd(&g_indeg[d[i]], wv);
        }
    }
}

// ---------------------------------------------------------------------------
// Kernel 3: per-node rsqrt, in place. deg==0 -> +inf, but such nodes never
// appear on the corresponding side of any edge, so the inf is never gathered.
// ---------------------------------------------------------------------------
__global__ void rsqrt_deg_kernel(const int* __restrict__ num_nodes) {
    int n = *num_nodes;
    int i = blockIdx.x * blockDim.x + threadIdx.x;
    if (i < n) {
        g_outdeg[i] = rsqrtf(g_outdeg[i]);
        g_indeg[i]  = rsqrtf(g_indeg[i]);
    }
}

// ---------------------------------------------------------------------------
// Kernel 4: per-edge gather-multiply. Norm arrays (800KB total) are fully
// L2-resident; random gathers are L2 hits hidden by MLP.
// ---------------------------------------------------------------------------
__global__ void gather_mul_kernel(const float4* __restrict__ w4,
                                  const int4*   __restrict__ s4,
                                  const int4*   __restrict__ d4,
                                  const float*  __restrict__ w,
                                  const int*    __restrict__ s,
                                  const int*    __restrict__ d,
                                  float4* __restrict__ out4,
                                  float*  __restrict__ out,
                                  int n4, int E) {
    int tid = blockIdx.x * blockDim.x + threadIdx.x;
    if (tid < n4) {
        float4 wv = w4[tid];
        int4   sv = s4[tid];
        int4   dv = d4[tid];
        float4 r;
        r.x = g_outdeg[sv.x] * g_indeg[dv.x] * wv.x;
        r.y = g_outdeg[sv.y] * g_indeg[dv.y] * wv.y;
        r.z = g_outdeg[sv.z] * g_indeg[dv.z] * wv.z;
        r.w = g_outdeg[sv.w] * g_indeg[dv.w] * wv.w;
        out4[tid] = r;
    } else {
        int i = 4 * n4 + (tid - n4);
        if (i < E) {
            out[i] = g_outdeg[s[i]] * g_indeg[d[i]] * w[i];
        }
    }
}

extern "C" void kernel_launch(void* const* d_in, const int* in_sizes, int n_in,
                              void* d_out, int out_size) {
    const float* w   = (const float*)d_in[0];
    const int*   src = (const int*)d_in[1];
    const int*   dst = (const int*)d_in[2];
    const int*   nn  = (const int*)d_in[3];  // num_nodes (device scalar)
    float* out = (float*)d_out;

    int E  = in_sizes[0];
    int n4 = E / 4;
    int nthreads = n4 + (E - 4 * n4);  // vector threads + scalar tail threads

    const int TPB = 256;

    zero_deg_kernel<<<(MAX_NODES + TPB - 1) / TPB, TPB>>>();

    scatter_deg_kernel<<<(nthreads + TPB - 1) / TPB, TPB>>>(
        (const float4*)w, (const int4*)src, (const int4*)dst,
        w, src, dst, n4, E);

    rsqrt_deg_kernel<<<(MAX_NODES + TPB - 1) / TPB, TPB>>>(nn);

    gather_mul_kernel<<<(nthreads + TPB - 1) / TPB, TPB>>>(
        (const float4*)w, (const int4*)src, (const int4*)dst,
        w, src, dst, (float4*)out, out, n4, E);
}